// round 11
// baseline (speedup 1.0000x reference)
#include <cuda_runtime.h>

// out[i] = Param_b[b_params[i]] + sum_{e: w_rows[e]==i} Param_W[w_params[e]] * x[w_cols[e]]
// N = 262144, E = 16777216, NPARAMS = 1280, NB = 16

#define NPARAMS 1280
#define TPB 256
#define GRID_CTAS (148 * 8)   // one full occupancy wave, persistent

// Fused persistent kernel. out has been zeroed by the memset node.
// Phase 1: bias via atomicAdd (commutes with edge reductions, no ordering
// needed across CTAs). Phase 2: grid-stride edge gather-scale-scatter,
// 8 edges per iteration. No cache-policy hints (measured harmful).
__global__ __launch_bounds__(TPB) void fused_kernel(
    float* __restrict__ out,
    const float* __restrict__ x,
    const float* __restrict__ Param_W,
    const float* __restrict__ Param_b,
    const int4* __restrict__ b_params4,
    const int4* __restrict__ rows4,
    const int4* __restrict__ cols4,
    const int4* __restrict__ params4,
    int n4,   // N/4
    int e8)   // E/8
{
    __shared__ float sW[NPARAMS];
    #pragma unroll
    for (int i = threadIdx.x; i < NPARAMS; i += TPB) {
        sW[i] = Param_W[i];
    }
    __syncthreads();

    const int tid0   = blockIdx.x * TPB + threadIdx.x;
    const int stride = gridDim.x * TPB;

    // ---- Phase 1: bias (atomic adds onto zeroed out) ----
    for (int i = tid0; i < n4; i += stride) {
        int4 b = __ldcs(&b_params4[i]);
        float v0 = __ldg(&Param_b[b.x]);
        float v1 = __ldg(&Param_b[b.y]);
        float v2 = __ldg(&Param_b[b.z]);
        float v3 = __ldg(&Param_b[b.w]);
        int base = i * 4;
        atomicAdd(&out[base + 0], v0);
        atomicAdd(&out[base + 1], v1);
        atomicAdd(&out[base + 2], v2);
        atomicAdd(&out[base + 3], v3);
    }

    // ---- Phase 2: edges, 8 per iteration ----
    for (int idx = tid0; idx < e8; idx += stride) {
        int4 c0 = __ldcs(&cols4[2 * idx]);
        int4 c1 = __ldcs(&cols4[2 * idx + 1]);

        // 8 independent gathers in flight.
        float x0 = __ldg(&x[c0.x]);
        float x1 = __ldg(&x[c0.y]);
        float x2 = __ldg(&x[c0.z]);
        float x3 = __ldg(&x[c0.w]);
        float x4 = __ldg(&x[c1.x]);
        float x5 = __ldg(&x[c1.y]);
        float x6 = __ldg(&x[c1.z]);
        float x7 = __ldg(&x[c1.w]);

        int4 p0 = __ldcs(&params4[2 * idx]);
        int4 p1 = __ldcs(&params4[2 * idx + 1]);
        int4 r0 = __ldcs(&rows4[2 * idx]);
        int4 r1 = __ldcs(&rows4[2 * idx + 1]);

        float w0 = sW[p0.x];
        float w1 = sW[p0.y];
        float w2 = sW[p0.z];
        float w3 = sW[p0.w];
        float w4 = sW[p1.x];
        float w5 = sW[p1.y];
        float w6 = sW[p1.z];
        float w7 = sW[p1.w];

        // Fire-and-forget reductions (REDG, no return value).
        atomicAdd(&out[r0.x], w0 * x0);
        atomicAdd(&out[r0.y], w1 * x1);
        atomicAdd(&out[r0.z], w2 * x2);
        atomicAdd(&out[r0.w], w3 * x3);
        atomicAdd(&out[r1.x], w4 * x4);
        atomicAdd(&out[r1.y], w5 * x5);
        atomicAdd(&out[r1.z], w6 * x6);
        atomicAdd(&out[r1.w], w7 * x7);
    }
}

extern "C" void kernel_launch(void* const* d_in, const int* in_sizes, int n_in,
                              void* d_out, int out_size) {
    const float* x       = (const float*)d_in[0];
    const float* Param_W = (const float*)d_in[1];
    const float* Param_b = (const float*)d_in[2];
    const int*   w_rows  = (const int*)d_in[3];
    const int*   w_cols  = (const int*)d_in[4];
    const int*   w_params= (const int*)d_in[5];
    const int*   b_params= (const int*)d_in[6];
    float* out = (float*)d_out;

    int N = out_size;              // 262144
    int E = in_sizes[3];           // 16777216

    // Zero the output; bias + edges are then pure commutative atomic adds.
    cudaMemsetAsync(out, 0, (size_t)N * sizeof(float));

    int n4 = N / 4;   // 65536
    int e8 = E / 8;   // 2097152

    fused_kernel<<<GRID_CTAS, TPB>>>(
        out, x, Param_W, Param_b,
        (const int4*)b_params,
        (const int4*)w_rows, (const int4*)w_cols, (const int4*)w_params,
        n4, e8);
}

// round 12
// speedup vs baseline: 1.1224x; 1.1224x over previous
#include <cuda_runtime.h>

// out[i] = Param_b[b_params[i]] + sum_{e: w_rows[e]==i} Param_W[w_params[e]] * x[w_cols[e]]
// N = 262144, E = 16777216, NPARAMS = 1280, NB = 16

#define NPARAMS 1280
#define TPB 256

// Fused single-launch kernel (many-CTA, NOT persistent — persistence measured
// -17µs due to tail imbalance; cache hints measured harmful and removed).
// out has been zeroed by the memset node, so bias can be applied with
// atomicAdd, which commutes with the edge reductions: no ordering needed
// between bias blocks and edge blocks.
__global__ __launch_bounds__(TPB) void fused_kernel(
    float* __restrict__ out,
    const float* __restrict__ x,
    const float* __restrict__ Param_W,
    const float* __restrict__ Param_b,
    const int4* __restrict__ b_params4,
    const int4* __restrict__ rows4,
    const int4* __restrict__ cols4,
    const int4* __restrict__ params4,
    int biasBlocks,   // leading blocks doing bias, 4 outputs/thread
    int e8)           // E/8
{
    if (blockIdx.x < (unsigned)biasBlocks) {
        int i = blockIdx.x * TPB + threadIdx.x;  // i in [0, N/4)
        int4 b = __ldcs(&b_params4[i]);
        float v0 = __ldg(&Param_b[b.x]);
        float v1 = __ldg(&Param_b[b.y]);
        float v2 = __ldg(&Param_b[b.z]);
        float v3 = __ldg(&Param_b[b.w]);
        int base = i * 4;
        atomicAdd(&out[base + 0], v0);
        atomicAdd(&out[base + 1], v1);
        atomicAdd(&out[base + 2], v2);
        atomicAdd(&out[base + 3], v3);
        return;
    }

    __shared__ float sW[NPARAMS];
    #pragma unroll
    for (int i = threadIdx.x; i < NPARAMS; i += TPB) {
        sW[i] = Param_W[i];
    }
    __syncthreads();

    int idx = (blockIdx.x - biasBlocks) * TPB + threadIdx.x;
    if (idx >= e8) return;

    int4 c0 = __ldcs(&cols4[2 * idx]);
    int4 c1 = __ldcs(&cols4[2 * idx + 1]);

    // 8 independent gathers in flight.
    float x0 = __ldg(&x[c0.x]);
    float x1 = __ldg(&x[c0.y]);
    float x2 = __ldg(&x[c0.z]);
    float x3 = __ldg(&x[c0.w]);
    float x4 = __ldg(&x[c1.x]);
    float x5 = __ldg(&x[c1.y]);
    float x6 = __ldg(&x[c1.z]);
    float x7 = __ldg(&x[c1.w]);

    int4 p0 = __ldcs(&params4[2 * idx]);
    int4 p1 = __ldcs(&params4[2 * idx + 1]);
    int4 r0 = __ldcs(&rows4[2 * idx]);
    int4 r1 = __ldcs(&rows4[2 * idx + 1]);

    float w0 = sW[p0.x];
    float w1 = sW[p0.y];
    float w2 = sW[p0.z];
    float w3 = sW[p0.w];
    float w4 = sW[p1.x];
    float w5 = sW[p1.y];
    float w6 = sW[p1.z];
    float w7 = sW[p1.w];

    // Fire-and-forget reductions (REDG, no return value).
    atomicAdd(&out[r0.x], w0 * x0);
    atomicAdd(&out[r0.y], w1 * x1);
    atomicAdd(&out[r0.z], w2 * x2);
    atomicAdd(&out[r0.w], w3 * x3);
    atomicAdd(&out[r1.x], w4 * x4);
    atomicAdd(&out[r1.y], w5 * x5);
    atomicAdd(&out[r1.z], w6 * x6);
    atomicAdd(&out[r1.w], w7 * x7);
}

extern "C" void kernel_launch(void* const* d_in, const int* in_sizes, int n_in,
                              void* d_out, int out_size) {
    const float* x       = (const float*)d_in[0];
    const float* Param_W = (const float*)d_in[1];
    const float* Param_b = (const float*)d_in[2];
    const int*   w_rows  = (const int*)d_in[3];
    const int*   w_cols  = (const int*)d_in[4];
    const int*   w_params= (const int*)d_in[5];
    const int*   b_params= (const int*)d_in[6];
    float* out = (float*)d_out;

    int N = out_size;              // 262144
    int E = in_sizes[3];           // 16777216

    // Zero the output; bias + edges become pure commutative atomic adds.
    cudaMemsetAsync(out, 0, (size_t)N * sizeof(float));

    int e8 = E / 8;                            // 2097152
    int biasBlocks = (N / 4 + TPB - 1) / TPB;  // 256
    int edgeBlocks = (e8 + TPB - 1) / TPB;     // 8192

    fused_kernel<<<biasBlocks + edgeBlocks, TPB>>>(
        out, x, Param_W, Param_b,
        (const int4*)b_params,
        (const int4*)w_rows, (const int4*)w_cols, (const int4*)w_params,
        biasBlocks, e8);
}